// round 2
// baseline (speedup 1.0000x reference)
#include <cuda_runtime.h>
#include <math.h>

// Problem constants
#define B_  16
#define C_  128
#define O_  256
#define H_  96
#define W_  96
#define KH  5
#define HO  92
#define WO  92
#define HW_IN  (H_*W_)        // 9216
#define HW_OUT (HO*WO)        // 8464
#define KK  (KH*KH)           // 25
#define CK  (C_*KK)           // 3200

// Scratch (device globals — no allocations allowed)
__device__ float g_Wt [C_*KK*O_];   // [c][k][o]   W transposed
__device__ float g_Wt2[C_*KK*O_];   // [c][k][o]   W^2 transposed
__device__ float g_T  [B_*HW_IN];   // per-pixel channel sum of (sigma + mu^2)
__device__ float g_S  [B_*HW_OUT];  // 5x5 box filter of g_T
__device__ float g_sp [O_];         // softplus(w_sigma)

// ---------------------------------------------------------------------------
// Prep: transpose weights to [c*25+k][o], square them, compute softplus.
// ---------------------------------------------------------------------------
__global__ void prep_kernel(const float* __restrict__ W,
                            const float* __restrict__ w_sigma) {
    int i = blockIdx.x * blockDim.x + threadIdx.x;
    if (i < O_) {
        float w = fmaxf(w_sigma[i], -88.0f);
        g_sp[i] = log1pf(expf(w));
    }
    if (i < O_*CK) {
        int o = i / CK;          // output channel
        int r = i - o * CK;      // c*25+k
        float w = W[i];          // coalesced read (W is [o][c][kh][kw])
        int dst = r * O_ + o;
        g_Wt [dst] = w;
        g_Wt2[dst] = w * w;
    }
}

// ---------------------------------------------------------------------------
// T[b,y,x] = sum_c ( sigma_x[b,c,y,x] + mu_x[b,c,y,x]^2 )
// ---------------------------------------------------------------------------
__global__ void chansum_kernel(const float* __restrict__ mu,
                               const float* __restrict__ sg) {
    int i = blockIdx.x * blockDim.x + threadIdx.x;
    if (i >= B_*HW_IN) return;
    int b = i / HW_IN;
    int p = i - b * HW_IN;
    const float* m = mu + (size_t)b * C_ * HW_IN + p;
    const float* s = sg + (size_t)b * C_ * HW_IN + p;
    float acc = 0.0f;
    #pragma unroll 8
    for (int c = 0; c < C_; ++c) {
        float mv = m[c * HW_IN];
        acc += s[c * HW_IN] + mv * mv;
    }
    g_T[i] = acc;
}

// ---------------------------------------------------------------------------
// S[b,y,x] = 5x5 box sum of T (VALID)
// ---------------------------------------------------------------------------
__global__ void boxsum_kernel() {
    int i = blockIdx.x * blockDim.x + threadIdx.x;
    if (i >= B_*HW_OUT) return;
    int b = i / HW_OUT;
    int p = i - b * HW_OUT;
    int y = p / WO;
    int x = p - y * WO;
    const float* t = g_T + b * HW_IN;
    float acc = 0.0f;
    #pragma unroll
    for (int dy = 0; dy < KH; ++dy)
        #pragma unroll
        for (int dx = 0; dx < KH; ++dx)
            acc += t[(y + dy) * W_ + (x + dx)];
    g_S[i] = acc;
}

// ---------------------------------------------------------------------------
// Main conv: implicit GEMM. Block tile = 128 o x (8 rows x 16 cols) pixels.
// 256 threads, thread tile 8o x 8px (one row, 8 consecutive cols).
// blockIdx.z encodes (b, og, path):  path 0 = mu conv(W), path 1 = sigma conv(W^2)
// ---------------------------------------------------------------------------
#define TROWS 8
#define TCOLS 16
#define INROWS (TROWS + KH - 1)   // 12
#define INCOLS (TCOLS + KH - 1)   // 20
#define INPITCH 21                // conflict-free pad

__global__ __launch_bounds__(256, 2)
void conv_kernel(const float* __restrict__ mu_x,
                 const float* __restrict__ sg_x,
                 const float* __restrict__ bias,
                 float* __restrict__ out) {
    int z    = blockIdx.z;
    int path = z & 1;
    int og   = (z >> 1) & 1;
    int b    = z >> 2;

    const float* x  = path ? sg_x  : mu_x;
    const float* wt = path ? g_Wt2 : g_Wt;

    int x0 = blockIdx.x * TCOLS;
    int y0 = blockIdx.y * TROWS;

    __shared__ float Wsm[KK * 128];          // [k][o_local 0..127]
    __shared__ float In [INROWS * INPITCH];  // padded input patch

    int tid  = threadIdx.x;
    int to   = tid >> 4;          // 0..15 -> 8 o's each
    int tp   = tid & 15;          // 0..15 pixel group
    int prow = tp >> 1;           // 0..7
    int pcb  = (tp & 1) * 8;      // 0 or 8

    float acc[8][8];
    #pragma unroll
    for (int a = 0; a < 8; ++a)
        #pragma unroll
        for (int j = 0; j < 8; ++j) acc[a][j] = 0.0f;

    const float* wbase = wt + og * 128;

    for (int c = 0; c < C_; ++c) {
        // --- stage weights: 25 x 128 floats, coalesced ---
        const float* wsrc = wbase + (size_t)c * KK * O_;
        #pragma unroll
        for (int i = tid; i < KK * 128; i += 256) {
            int k = i >> 7;
            int j = i & 127;
            Wsm[i] = wsrc[k * O_ + j];
        }
        // --- stage input patch 12x20 (zero-padded OOB) ---
        const float* xsrc = x + ((size_t)(b * C_ + c)) * HW_IN;
        if (tid < INROWS * INPITCH) {
            int r  = tid / INPITCH;
            int cc = tid - r * INPITCH;
            float v = 0.0f;
            int gy = y0 + r, gx = x0 + cc;
            if (cc < INCOLS && gy < H_ && gx < W_) v = xsrc[gy * W_ + gx];
            In[tid] = v;
        }
        __syncthreads();

        #pragma unroll
        for (int ki = 0; ki < KH; ++ki) {
            #pragma unroll
            for (int kj = 0; kj < KH; ++kj) {
                int k = ki * KH + kj;
                float wv[8];
                *(float4*)&wv[0] = *(const float4*)&Wsm[k * 128 + to * 8];
                *(float4*)&wv[4] = *(const float4*)&Wsm[k * 128 + to * 8 + 4];
                float iv[8];
                int base = (prow + ki) * INPITCH + pcb + kj;
                #pragma unroll
                for (int j = 0; j < 8; ++j) iv[j] = In[base + j];
                #pragma unroll
                for (int a = 0; a < 8; ++a)
                    #pragma unroll
                    for (int j = 0; j < 8; ++j)
                        acc[a][j] = fmaf(wv[a], iv[j], acc[a][j]);
            }
        }
        __syncthreads();
    }

    // --- epilogue ---
    int y = y0 + prow;
    if (y >= HO) return;

    if (path == 0) {
        #pragma unroll
        for (int a = 0; a < 8; ++a) {
            int o = og * 128 + to * 8 + a;
            float bz = bias[o];
            float* op = out + ((size_t)(b * O_ + o) * HO + y) * WO;
            #pragma unroll
            for (int j = 0; j < 8; ++j) {
                int xx = x0 + pcb + j;
                if (xx < WO) op[xx] = acc[a][j] + bz;
            }
        }
    } else {
        float* out2 = out + (size_t)B_ * O_ * HW_OUT;
        float sv[8];
        const float* srow = g_S + (b * HO + y) * WO;
        #pragma unroll
        for (int j = 0; j < 8; ++j) {
            int xx = x0 + pcb + j;
            sv[j] = (xx < WO) ? srow[xx] : 0.0f;
        }
        #pragma unroll
        for (int a = 0; a < 8; ++a) {
            int o = og * 128 + to * 8 + a;
            float spo = g_sp[o];
            float* op = out2 + ((size_t)(b * O_ + o) * HO + y) * WO;
            #pragma unroll
            for (int j = 0; j < 8; ++j) {
                int xx = x0 + pcb + j;
                if (xx < WO) op[xx] = (spo * sv[j] + acc[a][j]) * 0.001f;
            }
        }
    }
}

// ---------------------------------------------------------------------------
extern "C" void kernel_launch(void* const* d_in, const int* in_sizes, int n_in,
                              void* d_out, int out_size) {
    const float* mu_x    = (const float*)d_in[0];
    const float* sigma_x = (const float*)d_in[1];
    const float* W       = (const float*)d_in[2];
    const float* bias    = (const float*)d_in[3];
    const float* w_sigma = (const float*)d_in[4];
    float* out = (float*)d_out;

    {
        int n = O_ * CK;
        prep_kernel<<<(n + 255) / 256, 256>>>(W, w_sigma);
    }
    {
        int n = B_ * HW_IN;
        chansum_kernel<<<(n + 255) / 256, 256>>>(mu_x, sigma_x);
    }
    {
        int n = B_ * HW_OUT;
        boxsum_kernel<<<(n + 255) / 256, 256>>>();
    }
    {
        dim3 grid((WO + TCOLS - 1) / TCOLS,   // 6
                  (HO + TROWS - 1) / TROWS,   // 12
                  B_ * 2 * 2);                // b * og * path = 64
        conv_kernel<<<grid, 256>>>(mu_x, sigma_x, bias, out);
    }
}

// round 3
// speedup vs baseline: 1.1218x; 1.1218x over previous
#include <cuda_runtime.h>
#include <math.h>
#include <stdint.h>

// Problem constants
#define B_  16
#define C_  128
#define O_  256
#define H_  96
#define W_  96
#define KH  5
#define HO  92
#define WO  92
#define HW_IN  (H_*W_)        // 9216
#define HW_OUT (HO*WO)        // 8464
#define KK  (KH*KH)           // 25
#define CK  (C_*KK)           // 3200

// Scratch (device globals — no allocations allowed)
// Weight layout: [c][og][25][128]  (og = o>>7, ol = o&127) -> contiguous 12.8KB per (c,og)
__device__ float g_Wt [C_*2*KK*128];
__device__ float g_Wt2[C_*2*KK*128];
__device__ float g_T  [B_*HW_IN];   // per-pixel channel sum of (sigma + mu^2)
__device__ float g_S  [B_*HW_OUT];  // 5x5 box filter of g_T
__device__ float g_sp [O_];         // softplus(w_sigma)

// ---------------------------------------------------------------------------
__global__ void prep_kernel(const float* __restrict__ W,
                            const float* __restrict__ w_sigma) {
    int i = blockIdx.x * blockDim.x + threadIdx.x;
    if (i < O_) {
        float w = fmaxf(w_sigma[i], -88.0f);
        g_sp[i] = log1pf(expf(w));
    }
    if (i < O_*CK) {
        int o = i / CK;          // output channel
        int r = i - o * CK;      // c*25+k
        int c = r / KK;
        int k = r - c * KK;
        int og = o >> 7, ol = o & 127;
        float w = W[i];          // coalesced read (W is [o][c][kh][kw])
        int dst = ((c * 2 + og) * KK + k) * 128 + ol;
        g_Wt [dst] = w;
        g_Wt2[dst] = w * w;
    }
}

// ---------------------------------------------------------------------------
__global__ void chansum_kernel(const float* __restrict__ mu,
                               const float* __restrict__ sg) {
    int i = blockIdx.x * blockDim.x + threadIdx.x;
    if (i >= B_*HW_IN) return;
    int b = i / HW_IN;
    int p = i - b * HW_IN;
    const float* m = mu + (size_t)b * C_ * HW_IN + p;
    const float* s = sg + (size_t)b * C_ * HW_IN + p;
    float acc = 0.0f;
    #pragma unroll 8
    for (int c = 0; c < C_; ++c) {
        float mv = m[c * HW_IN];
        acc += s[c * HW_IN] + mv * mv;
    }
    g_T[i] = acc;
}

// ---------------------------------------------------------------------------
__global__ void boxsum_kernel() {
    int i = blockIdx.x * blockDim.x + threadIdx.x;
    if (i >= B_*HW_OUT) return;
    int b = i / HW_OUT;
    int p = i - b * HW_OUT;
    int y = p / WO;
    int x = p - y * WO;
    const float* t = g_T + b * HW_IN;
    float acc = 0.0f;
    #pragma unroll
    for (int dy = 0; dy < KH; ++dy)
        #pragma unroll
        for (int dx = 0; dx < KH; ++dx)
            acc += t[(y + dy) * W_ + (x + dx)];
    g_S[i] = acc;
}

// ---------------------------------------------------------------------------
// cp.async helpers
// ---------------------------------------------------------------------------
__device__ __forceinline__ void cp16(uint32_t dst, const void* src) {
    asm volatile("cp.async.ca.shared.global [%0], [%1], 16;\n"
                 :: "r"(dst), "l"(src));
}
__device__ __forceinline__ void cp4z(uint32_t dst, const void* src, int srcsz) {
    asm volatile("cp.async.ca.shared.global [%0], [%1], 4, %2;\n"
                 :: "r"(dst), "l"(src), "r"(srcsz));
}
__device__ __forceinline__ void cp_commit() {
    asm volatile("cp.async.commit_group;\n" ::: "memory");
}
__device__ __forceinline__ void cp_wait0() {
    asm volatile("cp.async.wait_group 0;\n" ::: "memory");
}

// ---------------------------------------------------------------------------
// Main conv: implicit GEMM, cp.async double-buffered pipeline.
// Block tile = 128 o x (8 rows x 16 cols) pixels, 256 thr, 8o x 8px per thread.
// blockIdx.z = (b, og, path):  path 0 = mu conv(W), path 1 = sigma conv(W^2)
// ---------------------------------------------------------------------------
#define TROWS 8
#define TCOLS 16
#define INROWS (TROWS + KH - 1)   // 12
#define INCOLS (TCOLS + KH - 1)   // 20
#define INPITCH 21                // conflict-free pad
#define INELEM (INROWS * INCOLS)  // 240

__global__ __launch_bounds__(256, 2)
void conv_kernel(const float* __restrict__ mu_x,
                 const float* __restrict__ sg_x,
                 const float* __restrict__ bias,
                 float* __restrict__ out) {
    int z    = blockIdx.z;
    int path = z & 1;
    int og   = (z >> 1) & 1;
    int b    = z >> 2;

    const float* x  = path ? sg_x  : mu_x;
    const float* wt = path ? g_Wt2 : g_Wt;

    int x0 = blockIdx.x * TCOLS;
    int y0 = blockIdx.y * TROWS;

    __shared__ float Wsm[2][KK * 128];          // [buf][k][o_local]
    __shared__ float In [2][INROWS * INPITCH];  // [buf][padded patch]

    int tid  = threadIdx.x;
    int to   = tid >> 4;          // 0..15 -> 8 o's each
    int tp   = tid & 15;
    int prow = tp >> 1;           // 0..7
    int pcb  = (tp & 1) * 8;      // 0 or 8

    // --- staging setup (invariant across c) ---
    const float* wblk = wt + (size_t)og * (KK * 128);       // + c*2*KK*128 per c
    const size_t wstride = (size_t)2 * KK * 128;

    int ir = tid / INCOLS;                 // 0..11   (valid when tid < 240)
    int ic = tid - ir * INCOLS;            // 0..19
    bool ivalid = (tid < INELEM) && (y0 + ir < H_) && (x0 + ic < W_);
    int gy = min(y0 + ir, H_ - 1);
    int gx = min(x0 + ic, W_ - 1);
    const float* ip0 = x + (size_t)b * C_ * HW_IN + gy * W_ + gx;
    int isrcsz = ivalid ? 4 : 0;
    int idst = ir * INPITCH + ic;

    uint32_t wsmA[2], insmA[2];
    wsmA[0]  = (uint32_t)__cvta_generic_to_shared(&Wsm[0][0]);
    wsmA[1]  = (uint32_t)__cvta_generic_to_shared(&Wsm[1][0]);
    insmA[0] = (uint32_t)__cvta_generic_to_shared(&In[0][0]);
    insmA[1] = (uint32_t)__cvta_generic_to_shared(&In[1][0]);

    // stage channel c into buffer buf
    auto stage = [&](int c, int buf) {
        const char* wsrc = (const char*)(wblk + (size_t)c * wstride);
        uint32_t wdst = wsmA[buf];
        cp16(wdst + tid * 16,         wsrc + tid * 16);
        cp16(wdst + (tid + 256) * 16, wsrc + (tid + 256) * 16);
        cp16(wdst + (tid + 512) * 16, wsrc + (tid + 512) * 16);
        if (tid < 32)
            cp16(wdst + (tid + 768) * 16, wsrc + (tid + 768) * 16);
        if (tid < INELEM)
            cp4z(insmA[buf] + idst * 4, ip0 + (size_t)c * HW_IN, isrcsz);
        cp_commit();
    };

    float acc[8][8];
    #pragma unroll
    for (int a = 0; a < 8; ++a)
        #pragma unroll
        for (int j = 0; j < 8; ++j) acc[a][j] = 0.0f;

    stage(0, 0);

    #pragma unroll 2
    for (int c = 0; c < C_; ++c) {
        cp_wait0();
        __syncthreads();
        if (c + 1 < C_) stage(c + 1, (c + 1) & 1);

        const float* Wb = Wsm[c & 1];
        const float* Ib = In [c & 1];

        #pragma unroll
        for (int ki = 0; ki < KH; ++ki) {
            float iv[12];
            int base = (prow + ki) * INPITCH + pcb;
            #pragma unroll
            for (int j = 0; j < 12; ++j) iv[j] = Ib[base + j];

            #pragma unroll
            for (int kj = 0; kj < KH; ++kj) {
                float wv[8];
                const float4* wp = (const float4*)&Wb[(ki * KH + kj) * 128 + to * 8];
                float4 w0 = wp[0], w1 = wp[1];
                wv[0] = w0.x; wv[1] = w0.y; wv[2] = w0.z; wv[3] = w0.w;
                wv[4] = w1.x; wv[5] = w1.y; wv[6] = w1.z; wv[7] = w1.w;
                #pragma unroll
                for (int a = 0; a < 8; ++a)
                    #pragma unroll
                    for (int j = 0; j < 8; ++j)
                        acc[a][j] = fmaf(wv[a], iv[kj + j], acc[a][j]);
            }
        }
    }

    // --- epilogue ---
    int y = y0 + prow;
    if (y >= HO) return;

    if (path == 0) {
        #pragma unroll
        for (int a = 0; a < 8; ++a) {
            int o = og * 128 + to * 8 + a;
            float bz = bias[o];
            float* op = out + ((size_t)(b * O_ + o) * HO + y) * WO;
            #pragma unroll
            for (int j = 0; j < 8; ++j) {
                int xx = x0 + pcb + j;
                if (xx < WO) op[xx] = acc[a][j] + bz;
            }
        }
    } else {
        float* out2 = out + (size_t)B_ * O_ * HW_OUT;
        float sv[8];
        const float* srow = g_S + (b * HO + y) * WO;
        #pragma unroll
        for (int j = 0; j < 8; ++j) {
            int xx = x0 + pcb + j;
            sv[j] = (xx < WO) ? srow[xx] : 0.0f;
        }
        #pragma unroll
        for (int a = 0; a < 8; ++a) {
            int o = og * 128 + to * 8 + a;
            float spo = g_sp[o];
            float* op = out2 + ((size_t)(b * O_ + o) * HO + y) * WO;
            #pragma unroll
            for (int j = 0; j < 8; ++j) {
                int xx = x0 + pcb + j;
                if (xx < WO) op[xx] = (spo * sv[j] + acc[a][j]) * 0.001f;
            }
        }
    }
}

// ---------------------------------------------------------------------------
extern "C" void kernel_launch(void* const* d_in, const int* in_sizes, int n_in,
                              void* d_out, int out_size) {
    const float* mu_x    = (const float*)d_in[0];
    const float* sigma_x = (const float*)d_in[1];
    const float* W       = (const float*)d_in[2];
    const float* bias    = (const float*)d_in[3];
    const float* w_sigma = (const float*)d_in[4];
    float* out = (float*)d_out;

    {
        int n = O_ * CK;
        prep_kernel<<<(n + 255) / 256, 256>>>(W, w_sigma);
    }
    {
        int n = B_ * HW_IN;
        chansum_kernel<<<(n + 255) / 256, 256>>>(mu_x, sigma_x);
    }
    {
        int n = B_ * HW_OUT;
        boxsum_kernel<<<(n + 255) / 256, 256>>>();
    }
    {
        dim3 grid((WO + TCOLS - 1) / TCOLS,   // 6
                  (HO + TROWS - 1) / TROWS,   // 12
                  B_ * 2 * 2);                // 64
        conv_kernel<<<grid, 256>>>(mu_x, sigma_x, bias, out);
    }
}

// round 5
// speedup vs baseline: 2.0018x; 1.7844x over previous
#include <cuda_runtime.h>
#include <cuda_bf16.h>
#include <math.h>
#include <stdint.h>

#define B_  16
#define C_  128
#define O_  256
#define H_  96
#define W_  96
#define KH  5
#define HO  92
#define WO  92
#define HW_IN  (H_*W_)        // 9216
#define HW_OUT (HO*WO)        // 8464
#define KK  25
#define NPT 67                // ceil(8464/128)
#define NSTAGE 50             // 25 taps * 2 k64-chunks

// ---------------- device scratch (no allocation allowed) ----------------
// Channel-last bf16 planes: [path][b][pix(9216)][c(128)]
__device__ __align__(128) __nv_bfloat16 g_Ah[(size_t)2*B_*HW_IN*128];
__device__ __align__(128) __nv_bfloat16 g_Al[(size_t)2*B_*HW_IN*128];
// Weights: [path][og][tap][split][o_local(128)][c(128)]  (16384 elems / block)
__device__ __align__(128) __nv_bfloat16 g_Wp[(size_t)2*2*KK*2*16384];
__device__ float g_T [B_*HW_IN];
__device__ float g_S [B_*HW_OUT];
__device__ float g_sp[O_];

// ---------------- PTX helpers ----------------
__device__ __forceinline__ uint32_t smem_u32(const void* p){
    return (uint32_t)__cvta_generic_to_shared((void*)p);
}
__device__ __forceinline__ void cp16(uint32_t dst, const void* src){
    asm volatile("cp.async.cg.shared.global [%0], [%1], 16;\n" :: "r"(dst), "l"(src));
}
__device__ __forceinline__ void cp_commit(){ asm volatile("cp.async.commit_group;\n" ::: "memory"); }
template<int N> __device__ __forceinline__ void cp_wait(){
    asm volatile("cp.async.wait_group %0;\n" :: "n"(N) : "memory");
}
__device__ __forceinline__ void ldsm4(uint32_t* r, uint32_t addr){
    asm volatile("ldmatrix.sync.aligned.m8n8.x4.shared.b16 {%0,%1,%2,%3}, [%4];"
        : "=r"(r[0]), "=r"(r[1]), "=r"(r[2]), "=r"(r[3]) : "r"(addr));
}
#define MMA(acc, a, b0, b1)                                                        \
    asm volatile("mma.sync.aligned.m16n8k16.row.col.f32.bf16.bf16.f32 "            \
                 "{%0,%1,%2,%3},{%4,%5,%6,%7},{%8,%9},{%0,%1,%2,%3};"              \
                 : "+f"((acc)[0]), "+f"((acc)[1]), "+f"((acc)[2]), "+f"((acc)[3])  \
                 : "r"((a)[0]), "r"((a)[1]), "r"((a)[2]), "r"((a)[3]),             \
                   "r"(b0), "r"(b1))

// ---------------- prep kernels ----------------
__global__ void transpose_split_kernel(const float* __restrict__ mu,
                                       const float* __restrict__ sg) {
    __shared__ float ts[C_][65];
    int pt = blockIdx.x, b = blockIdx.y, path = blockIdx.z;
    const float* src = (path ? sg : mu) + (size_t)b * C_ * HW_IN + pt * 64;
    int tid = threadIdx.x;
    for (int i = tid; i < C_ * 64; i += 256) {
        int c = i >> 6, pi = i & 63;
        ts[c][pi] = src[(size_t)c * HW_IN + pi];
    }
    __syncthreads();
    size_t obase = (size_t)(path * B_ + b) * HW_IN * 128;
    int p0 = pt * 64;
    for (int i = tid; i < 64 * C_; i += 256) {
        int pi = i >> 7, c = i & 127;
        float v = ts[c][pi];
        __nv_bfloat16 hi = __float2bfloat16(v);
        __nv_bfloat16 lo = __float2bfloat16(v - __bfloat162float(hi));
        size_t idx = obase + (size_t)(p0 + pi) * 128 + c;
        g_Ah[idx] = hi;
        g_Al[idx] = lo;
    }
}

__global__ void wprep_kernel(const float* __restrict__ W,
                             const float* __restrict__ w_sigma) {
    int gid = blockIdx.x * blockDim.x + threadIdx.x;
    if (gid < O_) {
        float w = fmaxf(w_sigma[gid], -88.0f);
        g_sp[gid] = log1pf(expf(w));
    }
    if (gid >= O_ * C_) return;
    int o = gid >> 7, c = gid & 127;
    int og = o >> 7, ol = o & 127;
    const float* wp = W + ((size_t)o * C_ + c) * KK;
    int dst_in = ol * 128 + c;
    #pragma unroll
    for (int tap = 0; tap < KK; ++tap) {
        float w  = wp[tap];
        float w2 = w * w;
        __nv_bfloat16 h0 = __float2bfloat16(w);
        __nv_bfloat16 l0 = __float2bfloat16(w  - __bfloat162float(h0));
        __nv_bfloat16 h1 = __float2bfloat16(w2);
        __nv_bfloat16 l1 = __float2bfloat16(w2 - __bfloat162float(h1));
        size_t blk0 = (size_t)(((0 * 2 + og) * KK + tap) * 2);
        size_t blk1 = (size_t)(((1 * 2 + og) * KK + tap) * 2);
        g_Wp[(blk0 + 0) * 16384 + dst_in] = h0;
        g_Wp[(blk0 + 1) * 16384 + dst_in] = l0;
        g_Wp[(blk1 + 0) * 16384 + dst_in] = h1;
        g_Wp[(blk1 + 1) * 16384 + dst_in] = l1;
    }
}

__global__ void chansum_kernel(const float* __restrict__ mu,
                               const float* __restrict__ sg) {
    int i = blockIdx.x * blockDim.x + threadIdx.x;
    if (i >= B_*HW_IN) return;
    int b = i / HW_IN;
    int p = i - b * HW_IN;
    const float* m = mu + (size_t)b * C_ * HW_IN + p;
    const float* s = sg + (size_t)b * C_ * HW_IN + p;
    float acc = 0.0f;
    #pragma unroll 8
    for (int c = 0; c < C_; ++c) {
        float mv = m[c * HW_IN];
        acc += s[c * HW_IN] + mv * mv;
    }
    g_T[i] = acc;
}

__global__ void boxsum_kernel() {
    int i = blockIdx.x * blockDim.x + threadIdx.x;
    if (i >= B_*HW_OUT) return;
    int b = i / HW_OUT;
    int p = i - b * HW_OUT;
    int y = p / WO;
    int x = p - y * WO;
    const float* t = g_T + b * HW_IN;
    float acc = 0.0f;
    #pragma unroll
    for (int dy = 0; dy < KH; ++dy)
        #pragma unroll
        for (int dx = 0; dx < KH; ++dx)
            acc += t[(y + dy) * W_ + (x + dx)];
    g_S[i] = acc;
}

// ---------------- main mma.sync conv ----------------
// SMEM per buffer: Ah 16K | Al 16K | Bh 16K | Bl 16K = 64KB; 2 buffers = 128KB.
#define BUFSZ 65536u
#define OFF_AH 0u
#define OFF_AL 16384u
#define OFF_BH 32768u
#define OFF_BL 49152u
#define SMEM_MAIN 131072

__global__ void __launch_bounds__(256, 1)
mma_conv_kernel(const float* __restrict__ bias, float* __restrict__ out) {
    extern __shared__ char smem[];
    uint32_t sb = smem_u32(smem);
    int tid = threadIdx.x;
    int lane = tid & 31, wid = tid >> 5;
    int warp_m = wid >> 2, warp_n = wid & 3;

    int ptile = blockIdx.x, b = blockIdx.y;
    int path = blockIdx.z & 1, og = blockIdx.z >> 1;

    // ---- staging setup ----
    int m_pix = tid & 127;                       // pixel row this thread stages
    int p  = ptile * 128 + m_pix;
    int pc = min(p, HW_OUT - 1);
    int py = pc / WO, px = pc - py * WO;
    const __nv_bfloat16* aplane =
        (tid < 128 ? g_Ah : g_Al) + (size_t)(path * B_ + b) * HW_IN * 128;
    uint32_t a_sm_off = (tid < 128 ? OFF_AH : OFF_AL) + (uint32_t)m_pix * 128;

    int bn = tid >> 1, bhalf = tid & 1;          // weight row n, half of 128B
    const char* wbase = (const char*)g_Wp +
        (size_t)((path * 2 + og) * KK) * 2 * 32768 + (size_t)bn * 256 + bhalf * 64;
    uint32_t b_sm_base = (uint32_t)bn * 128;

    // stage (tap, kc) into buffer buf
    auto stage = [&](int s, int buf) {
        int tap = s >> 1, kc = s & 1;
        int ki = tap / 5, kj = tap - ki * 5;
        // A: 128B of channel-last row for shifted pixel
        const char* arow = (const char*)(aplane + ((size_t)((py + ki) * W_ + (px + kj))) * 128)
                           + kc * 128;
        uint32_t adst = sb + buf * BUFSZ + a_sm_off;
        int msw = m_pix & 7;
        #pragma unroll
        for (int j = 0; j < 8; ++j)
            cp16(adst + (uint32_t)((j ^ msw) << 4), arow + j * 16);
        // B: hi + lo weight blocks for this tap
        const char* bsrc = wbase + (size_t)tap * 2 * 32768 + kc * 128;
        uint32_t bdst = sb + buf * BUFSZ + b_sm_base;
        int nsw = bn & 7;
        #pragma unroll
        for (int j = 0; j < 4; ++j) {
            uint32_t so = (uint32_t)(((bhalf * 4 + j) ^ nsw) << 4);
            cp16(bdst + OFF_BH + so, bsrc + j * 16);
            cp16(bdst + OFF_BL + so, bsrc + 32768 + j * 16);
        }
        cp_commit();
    };

    // ---- ldmatrix address bases (lane-invariant parts) ----
    uint32_t rowbaseA = (uint32_t)(warp_m * 64 + (lane & 15)) * 128;
    uint32_t rowbaseB = (uint32_t)(warp_n * 32 + ((lane >> 4) << 3) + (lane & 7)) * 128;
    int lsw = lane & 7;
    uint32_t offA[4], offB[4];
    #pragma unroll
    for (int s = 0; s < 4; ++s) {
        offA[s] = (uint32_t)(((2 * s + (lane >> 4)) ^ lsw) << 4);
        offB[s] = (uint32_t)(((2 * s + ((lane >> 3) & 1)) ^ lsw) << 4);
    }

    float acc[4][4][4];
    #pragma unroll
    for (int mi = 0; mi < 4; ++mi)
        #pragma unroll
        for (int ni = 0; ni < 4; ++ni)
            #pragma unroll
            for (int j = 0; j < 4; ++j) acc[mi][ni][j] = 0.0f;

    stage(0, 0);

    for (int s = 0; s < NSTAGE; ++s) {
        int buf = s & 1;
        if (s + 1 < NSTAGE) { stage(s + 1, buf ^ 1); cp_wait<1>(); }
        else                { cp_wait<0>(); }
        __syncthreads();

        uint32_t base = sb + buf * BUFSZ;
        uint32_t aAh = base + OFF_AH + rowbaseA;
        uint32_t aAl = base + OFF_AL + rowbaseA;
        uint32_t aBh = base + OFF_BH + rowbaseB;
        uint32_t aBl = base + OFF_BL + rowbaseB;

        #pragma unroll
        for (int ks = 0; ks < 4; ++ks) {
            uint32_t ah[4][4], al[4][4], bh[2][4], bl[2][4];
            #pragma unroll
            for (int mi = 0; mi < 4; ++mi) {
                ldsm4(ah[mi], aAh + mi * 2048 + offA[ks]);
                ldsm4(al[mi], aAl + mi * 2048 + offA[ks]);
            }
            #pragma unroll
            for (int n2 = 0; n2 < 2; ++n2) {
                ldsm4(bh[n2], aBh + n2 * 2048 + offB[ks]);
                ldsm4(bl[n2], aBl + n2 * 2048 + offB[ks]);
            }
            #pragma unroll
            for (int mi = 0; mi < 4; ++mi)
                #pragma unroll
                for (int n2 = 0; n2 < 2; ++n2) {
                    MMA(acc[mi][2*n2],   ah[mi], bh[n2][0], bh[n2][1]);
                    MMA(acc[mi][2*n2+1], ah[mi], bh[n2][2], bh[n2][3]);
                    MMA(acc[mi][2*n2],   al[mi], bh[n2][0], bh[n2][1]);
                    MMA(acc[mi][2*n2+1], al[mi], bh[n2][2], bh[n2][3]);
                    MMA(acc[mi][2*n2],   ah[mi], bl[n2][0], bl[n2][1]);
                    MMA(acc[mi][2*n2+1], ah[mi], bl[n2][2], bl[n2][3]);
                }
        }
        __syncthreads();
    }

    // ---- epilogue: transpose via SMEM, coalesced float4 stores ----
    float* eps = (float*)smem;                 // [n=128][m pitch 132]
    #pragma unroll
    for (int mi = 0; mi < 4; ++mi) {
        int m0 = warp_m * 64 + mi * 16 + (lane >> 2);
        #pragma unroll
        for (int ni = 0; ni < 4; ++ni) {
            int n0 = warp_n * 32 + ni * 8 + 2 * (lane & 3);
            eps[n0 * 132 + m0]           = acc[mi][ni][0];
            eps[(n0 + 1) * 132 + m0]     = acc[mi][ni][1];
            eps[n0 * 132 + m0 + 8]       = acc[mi][ni][2];
            eps[(n0 + 1) * 132 + m0 + 8] = acc[mi][ni][3];
        }
    }
    __syncthreads();

    int pix0 = ptile * 128;
    int m = lane * 4;
    bool ok = (pix0 + m) < HW_OUT;
    if (path == 0) {
        #pragma unroll 1
        for (int rr = 0; rr < 16; ++rr) {
            int r = rr * 8 + wid;
            int o = og * 128 + r;
            float4 v = *(float4*)&eps[r * 132 + m];
            float bz = bias[o];
            v.x += bz; v.y += bz; v.z += bz; v.w += bz;
            if (ok)
                *(float4*)&out[((size_t)(b * O_ + o)) * HW_OUT + pix0 + m] = v;
        }
    } else {
        float* out2 = out + (size_t)B_ * O_ * HW_OUT;
        float4 sv = make_float4(0.f, 0.f, 0.f, 0.f);
        if (ok) sv = *(float4*)&g_S[(size_t)b * HW_OUT + pix0 + m];
        #pragma unroll 1
        for (int rr = 0; rr < 16; ++rr) {
            int r = rr * 8 + wid;
            int o = og * 128 + r;
            float4 v = *(float4*)&eps[r * 132 + m];
            float sp = g_sp[o];
            v.x = (sp * sv.x + v.x) * 0.001f;
            v.y = (sp * sv.y + v.y) * 0.001f;
            v.z = (sp * sv.z + v.z) * 0.001f;
            v.w = (sp * sv.w + v.w) * 0.001f;
            if (ok)
                *(float4*)&out2[((size_t)(b * O_ + o)) * HW_OUT + pix0 + m] = v;
        }
    }
}

// ---------------------------------------------------------------------------
extern "C" void kernel_launch(void* const* d_in, const int* in_sizes, int n_in,
                              void* d_out, int out_size) {
    const float* mu_x    = (const float*)d_in[0];
    const float* sigma_x = (const float*)d_in[1];
    const float* W       = (const float*)d_in[2];
    const float* bias    = (const float*)d_in[3];
    const float* w_sigma = (const float*)d_in[4];
    float* out = (float*)d_out;

    // immediate (non-captured) API; safe and idempotent
    cudaFuncSetAttribute(mma_conv_kernel,
                         cudaFuncAttributeMaxDynamicSharedMemorySize, SMEM_MAIN);

    {
        dim3 g(HW_IN / 64, B_, 2);                 // 144 x 16 x 2
        transpose_split_kernel<<<g, 256>>>(mu_x, sigma_x);
    }
    wprep_kernel<<<(O_ * C_ + 255) / 256, 256>>>(W, w_sigma);
    {
        int n = B_ * HW_IN;
        chansum_kernel<<<(n + 255) / 256, 256>>>(mu_x, sigma_x);
    }
    {
        int n = B_ * HW_OUT;
        boxsum_kernel<<<(n + 255) / 256, 256>>>();
    }
    {
        dim3 grid(NPT, B_, 4);                     // 67 x 16 x 4 = 4288 CTAs
        mma_conv_kernel<<<grid, 256, SMEM_MAIN>>>(bias, out);
    }
}